// round 5
// baseline (speedup 1.0000x reference)
#include <cuda_runtime.h>
#include <math.h>

#define NN 50000
#define EE 800000
#define INDIM 256
#define HH 128
#define LL 4
#define CC 230
#define WYD 26
#define SLAB ((size_t)NN * HH)

// ------------------------- device scratch (no allocations allowed) -------------------------
__device__ float g_states[(size_t)(LL + 1) * NN * HH];  // h after each layer (slab l)
__device__ float g_m[(size_t)NN * HH];                  // message accumulator
__device__ float g_t1[(size_t)NN * HH];                 // h_agg
__device__ float g_h[(size_t)NN * HH];                  // silu(o1) temp
__device__ float g_eenc[(size_t)EE * HH];               // edge encodings
__device__ float g_r[EE];
__device__ unsigned g_hist[65536];
__device__ unsigned g_histlo[2 * 65536];
__device__ unsigned g_selhi[2];
__device__ unsigned g_rem[2];
__device__ float g_cand[2];
__device__ float g_rmax;
__device__ int g_gid[NN];
__device__ float g_gsum[WYD * CC];
__device__ float g_gcnt[WYD];
__device__ float g_gmean[WYD * CC];

__device__ __forceinline__ float siluf(float v) { return v / (1.0f + __expf(-v)); }
__device__ __forceinline__ float warp_sum(float v) {
#pragma unroll
  for (int o = 16; o > 0; o >>= 1) v += __shfl_xor_sync(0xffffffffu, v, o);
  return v;
}

// ------------------------- zero kernel (replay idempotence) -------------------------
__global__ void k_zero_misc() {
  int i = blockIdx.x * blockDim.x + threadIdx.x;
  if (i < 65536) g_hist[i] = 0u;
  if (i < 2 * 65536) g_histlo[i] = 0u;
  if (i < WYD * CC) g_gsum[i] = 0.f;
  if (i < WYD) g_gcnt[i] = 0.f;
}
__global__ void k_zero_m() {
  size_t i = (size_t)blockIdx.x * blockDim.x + threadIdx.x;
  size_t tot = (size_t)NN * HH / 4;
  float4 z = make_float4(0.f, 0.f, 0.f, 0.f);
  for (; i < tot; i += (size_t)gridDim.x * blockDim.x) ((float4*)g_m)[i] = z;
}

// ------------------------- edge r + hi-histogram (fused) -------------------------
__global__ void k_edge_r_hist(const float* __restrict__ ea) {
  int e = blockIdx.x * blockDim.x + threadIdx.x;
  if (e >= EE) return;
  float ax = ea[e * 3 + 0], ay = ea[e * 3 + 1], az = ea[e * 3 + 2];
  float r = fmaxf(sqrtf(ax * ax + ay * ay + az * az), 1e-8f);
  g_r[e] = r;
  unsigned key = __float_as_uint(r);  // positive floats: bit order == value order
  atomicAdd(&g_hist[key >> 16], 1u);
}
__global__ void k_select_hi() {
  __shared__ unsigned s[1024];
  int tid = threadIdx.x;
  unsigned local = 0;
  for (int i = 0; i < 64; i++) local += g_hist[tid * 64 + i];
  s[tid] = local;
  __syncthreads();
  for (int off = 1; off < 1024; off <<= 1) {
    unsigned v = (tid >= off) ? s[tid - off] : 0u;
    __syncthreads();
    s[tid] += v;
    __syncthreads();
  }
  unsigned incl = s[tid], excl = incl - local;
  unsigned ranks[2] = {759999u, 760000u};  // floor/ceil of 0.95*(E-1)
  for (int j = 0; j < 2; j++) {
    unsigned R = ranks[j];
    if (R >= excl && R < incl) {
      unsigned cum = excl;
      for (int i = 0; i < 64; i++) {
        unsigned c = g_hist[tid * 64 + i];
        if (R < cum + c) { g_selhi[j] = (unsigned)(tid * 64 + i); g_rem[j] = R - cum; break; }
        cum += c;
      }
    }
  }
}
__global__ void k_histlo() {
  int e = blockIdx.x * blockDim.x + threadIdx.x;
  if (e >= EE) return;
  unsigned key = __float_as_uint(g_r[e]);
  unsigned hi = key >> 16, lo = key & 0xffffu;
  if (hi == g_selhi[0]) atomicAdd(&g_histlo[lo], 1u);
  if (hi == g_selhi[1]) atomicAdd(&g_histlo[65536 + lo], 1u);
}
__global__ void k_select_lo() {
  __shared__ unsigned s[1024];
  int tid = threadIdx.x;
  for (int j = 0; j < 2; j++) {
    const unsigned* h = g_histlo + j * 65536;
    unsigned local = 0;
    for (int i = 0; i < 64; i++) local += h[tid * 64 + i];
    s[tid] = local;
    __syncthreads();
    for (int off = 1; off < 1024; off <<= 1) {
      unsigned v = (tid >= off) ? s[tid - off] : 0u;
      __syncthreads();
      s[tid] += v;
      __syncthreads();
    }
    unsigned incl = s[tid], excl = incl - local;
    unsigned R = g_rem[j];
    if (R >= excl && R < incl) {
      unsigned cum = excl;
      for (int i = 0; i < 64; i++) {
        unsigned c = h[tid * 64 + i];
        if (R < cum + c) {
          g_cand[j] = __uint_as_float((g_selhi[j] << 16) | (unsigned)(tid * 64 + i));
          break;
        }
        cum += c;
      }
    }
    __syncthreads();
  }
  if (tid == 0) {
    // match JAX fp32 quantile arithmetic: index = q*(n-1) in f32
    float pos = 0.95f * (float)(EE - 1);
    float fl = floorf(pos);
    float frac = pos - fl;
    float v = g_cand[0] * (1.0f - frac) + g_cand[1] * frac;
    g_rmax = fminf(fmaxf(v, 1.0f), 8.0f);
  }
}

// ------------------------- edge encoder: e_enc = LN(silu([u,r,rbf] @ W_e + b_e)) -------------------------
__global__ __launch_bounds__(256) void k_edge_enc(const float* __restrict__ ea,
                                                  const float* __restrict__ We,
                                                  const float* __restrict__ be,
                                                  const float* __restrict__ ge,
                                                  const float* __restrict__ bee) {
  int e = blockIdx.x * 8 + (threadIdx.x >> 5);
  int lane = threadIdx.x & 31;
  if (e >= EE) return;  // uniform per warp
  float r = g_r[e];
  float inv = 1.0f / r;
  float comp = (lane < 3) ? ea[e * 3 + lane] : 0.f;
  float rmax = g_rmax;
  float d = fmaxf(rmax * (1.0f / 15.0f), 0.001f);
  float gamma = 1.0f / (0.5f * d * d);  // == 1/(2*(0.5*delta)^2)
  float fv = 0.f;
  if (lane < 3) fv = comp * inv;
  else if (lane == 3) fv = r;
  else if (lane < 20) {
    int k = lane - 4;
    float c = rmax * ((float)k / 15.0f);
    float t = r - c;
    fv = __expf(-gamma * t * t);
  }
  float4 acc = *(const float4*)&be[lane * 4];
#pragma unroll
  for (int k = 0; k < 20; k++) {
    float a = __shfl_sync(0xffffffffu, fv, k);
    float4 wv = *(const float4*)&We[k * HH + lane * 4];
    acc.x = fmaf(a, wv.x, acc.x);
    acc.y = fmaf(a, wv.y, acc.y);
    acc.z = fmaf(a, wv.z, acc.z);
    acc.w = fmaf(a, wv.w, acc.w);
  }
  acc.x = siluf(acc.x); acc.y = siluf(acc.y); acc.z = siluf(acc.z); acc.w = siluf(acc.w);
  float mu = warp_sum(acc.x + acc.y + acc.z + acc.w) * (1.0f / 128.0f);
  float d0 = acc.x - mu, d1 = acc.y - mu, d2 = acc.z - mu, d3 = acc.w - mu;
  float var = warp_sum(d0 * d0 + d1 * d1 + d2 * d2 + d3 * d3) * (1.0f / 128.0f);
  float rs = rsqrtf(var + 1e-5f);
  float4 gv = *(const float4*)&ge[lane * 4];
  float4 bv = *(const float4*)&bee[lane * 4];
  float4 o;
  o.x = d0 * rs * gv.x + bv.x;
  o.y = d1 * rs * gv.y + bv.y;
  o.z = d2 * rs * gv.z + bv.z;
  o.w = d3 * rs * gv.w + bv.w;
  *(float4*)&g_eenc[(size_t)e * HH + lane * 4] = o;
}

// ------------------------- fused edge message layer + scatter -------------------------
// 64 edges/block, 256 threads. GEMM1: (64x384)@(384x128) -> silu -> GEMM2: (64x128)@(128x128)
// -> silu -> atomicAdd into g_m[dst].
__global__ __launch_bounds__(256) void k_edge_layer(const int* __restrict__ ei,
                                                    const float* __restrict__ W1,
                                                    const float* __restrict__ b1,
                                                    const float* __restrict__ W2,
                                                    const float* __restrict__ b2, int l) {
  __shared__ __align__(16) float Bs[16][128];  // 8KB
  __shared__ __align__(16) float Cs[64][128];  // 32KB
  float(*As)[16] = (float(*)[16]) & Cs[0][0];  // alias: 64x16 floats = rows 0..7 of Cs
  int* sSrc = (int*)&Cs[8][0];                 // row 8 of Cs: 64+64 ints
  int* sDst = sSrc + 64;
  const float* h = g_states + (size_t)l * SLAB;
  int tid = threadIdx.x;
  int tr = tid >> 5, tc = tid & 31;
  int e0 = blockIdx.x * 64;
  if (tid < 64) sSrc[tid] = ei[e0 + tid];
  else if (tid < 128) sDst[tid - 64] = ei[EE + e0 + (tid - 64)];
  float4 bb = *(const float4*)&b1[tc * 4];   // hoisted bias loads (overlap with GEMM)
  float4 bb2 = *(const float4*)&b2[tc * 4];
  float acc[8][4];
#pragma unroll
  for (int i = 0; i < 8; i++) { acc[i][0] = 0.f; acc[i][1] = 0.f; acc[i][2] = 0.f; acc[i][3] = 0.f; }
#pragma unroll 1
  for (int c = 0; c < 24; c++) {
    int col0 = c * 16;
    __syncthreads();
    {
      int row = tid >> 2, q = tid & 3;
      const float* p;
      if (col0 < 128) p = h + (size_t)sSrc[row] * HH + col0;
      else if (col0 < 256) p = h + (size_t)sDst[row] * HH + (col0 - 128);
      else p = g_eenc + (size_t)(e0 + row) * HH + (col0 - 256);
      *(float4*)&As[row][q * 4] = *(const float4*)(p + q * 4);
    }
#pragma unroll
    for (int it = 0; it < 2; it++) {
      int idx = tid * 2 + it;
      int rr = idx >> 5, cc = idx & 31;
      *(float4*)&Bs[rr][cc * 4] = *(const float4*)(W1 + (size_t)(col0 + rr) * HH + cc * 4);
    }
    __syncthreads();
#pragma unroll
    for (int k = 0; k < 16; k++) {
      float4 b = *(float4*)&Bs[k][tc * 4];
#pragma unroll
      for (int i = 0; i < 8; i++) {
        float a = As[tr * 8 + i][k];
        acc[i][0] = fmaf(a, b.x, acc[i][0]);
        acc[i][1] = fmaf(a, b.y, acc[i][1]);
        acc[i][2] = fmaf(a, b.z, acc[i][2]);
        acc[i][3] = fmaf(a, b.w, acc[i][3]);
      }
    }
  }
  // snapshot this thread's dst indices BEFORE Cs clobbers row 8 (reads precede the
  // barrier; all Cs writes happen after it)
  int dstv[8];
#pragma unroll
  for (int i = 0; i < 8; i++) dstv[i] = sDst[tr * 8 + i];
  __syncthreads();  // all warps done reading As/sDst before Cs writes
  {
#pragma unroll
    for (int i = 0; i < 8; i++) {
      float4 v;
      v.x = siluf(acc[i][0] + bb.x);
      v.y = siluf(acc[i][1] + bb.y);
      v.z = siluf(acc[i][2] + bb.z);
      v.w = siluf(acc[i][3] + bb.w);
      *(float4*)&Cs[tr * 8 + i][tc * 4] = v;
      acc[i][0] = 0.f; acc[i][1] = 0.f; acc[i][2] = 0.f; acc[i][3] = 0.f;
    }
  }
#pragma unroll 1
  for (int c = 0; c < 8; c++) {
    __syncthreads();
#pragma unroll
    for (int it = 0; it < 2; it++) {
      int idx = tid * 2 + it;
      int rr = idx >> 5, cc = idx & 31;
      *(float4*)&Bs[rr][cc * 4] = *(const float4*)(W2 + (size_t)(c * 16 + rr) * HH + cc * 4);
    }
    __syncthreads();
#pragma unroll
    for (int k = 0; k < 16; k++) {
      float4 b = *(float4*)&Bs[k][tc * 4];
#pragma unroll
      for (int i = 0; i < 8; i++) {
        float a = Cs[tr * 8 + i][c * 16 + k];
        acc[i][0] = fmaf(a, b.x, acc[i][0]);
        acc[i][1] = fmaf(a, b.y, acc[i][1]);
        acc[i][2] = fmaf(a, b.z, acc[i][2]);
        acc[i][3] = fmaf(a, b.w, acc[i][3]);
      }
    }
  }
#pragma unroll
  for (int i = 0; i < 8; i++) {
    float* mp = g_m + (size_t)dstv[i] * HH + tc * 4;
    atomicAdd(mp + 0, siluf(acc[i][0] + bb2.x));
    atomicAdd(mp + 1, siluf(acc[i][1] + bb2.y));
    atomicAdd(mp + 2, siluf(acc[i][2] + bb2.z));
    atomicAdd(mp + 3, siluf(acc[i][3] + bb2.w));
  }
}

// ------------------------- node-side block GEMMs -------------------------
// MODE 0: out = silu(LN(x @ W + b))              (A = x, K=256)      -> states[0]
// MODE 1: out = LN(silu([h,m] @ W + b) + h)      (K=256)             -> states[l+1]
// MODE 2: out = concat(states) @ W + b           (K=640)             -> g_t1
// MODE 3: out = silu(g_t1 @ W + b)               (K=128)             -> g_h
template <int KD, int MODE>
__global__ __launch_bounds__(256) void k_gemm_node(const float* __restrict__ Ain,
                                                   const float* __restrict__ W,
                                                   const float* __restrict__ bias,
                                                   const float* __restrict__ gg,
                                                   const float* __restrict__ bb, int l) {
  __shared__ __align__(16) float Bs[16][128];
  __shared__ __align__(16) float As[64][16];
  int tid = threadIdx.x;
  int tr = tid >> 5, tc = tid & 31;
  int n0 = blockIdx.x * 64;
  const float* A0;
  const float* A1 = nullptr;
  float* out;
  if (MODE == 0) { A0 = Ain; out = g_states; }
  else if (MODE == 1) { A0 = g_states + (size_t)l * SLAB; A1 = g_m; out = g_states + (size_t)(l + 1) * SLAB; }
  else if (MODE == 2) { A0 = g_states; out = g_t1; }
  else { A0 = g_t1; out = g_h; }
  float acc[8][4];
#pragma unroll
  for (int i = 0; i < 8; i++) { acc[i][0] = 0.f; acc[i][1] = 0.f; acc[i][2] = 0.f; acc[i][3] = 0.f; }
#pragma unroll 1
  for (int c = 0; c < KD / 16; c++) {
    int col0 = c * 16;
    __syncthreads();
    {
      int row = tid >> 2, q = tid & 3;
      int n = n0 + row;
      if (n >= NN) n = NN - 1;
      const float* p;
      if (MODE == 0) p = A0 + (size_t)n * INDIM + col0;
      else if (MODE == 1) p = (col0 < 128) ? (A0 + (size_t)n * HH + col0) : (A1 + (size_t)n * HH + (col0 - 128));
      else if (MODE == 2) p = A0 + (size_t)(col0 >> 7) * SLAB + (size_t)n * HH + (col0 & 127);
      else p = A0 + (size_t)n * HH + col0;
      *(float4*)&As[row][q * 4] = *(const float4*)(p + q * 4);
    }
#pragma unroll
    for (int it = 0; it < 2; it++) {
      int idx = tid * 2 + it;
      int rr = idx >> 5, cc = idx & 31;
      *(float4*)&Bs[rr][cc * 4] = *(const float4*)(W + (size_t)(col0 + rr) * HH + cc * 4);
    }
    __syncthreads();
#pragma unroll
    for (int k = 0; k < 16; k++) {
      float4 b = *(float4*)&Bs[k][tc * 4];
#pragma unroll
      for (int i = 0; i < 8; i++) {
        float a = As[tr * 8 + i][k];
        acc[i][0] = fmaf(a, b.x, acc[i][0]);
        acc[i][1] = fmaf(a, b.y, acc[i][1]);
        acc[i][2] = fmaf(a, b.z, acc[i][2]);
        acc[i][3] = fmaf(a, b.w, acc[i][3]);
      }
    }
  }
  float4 bv = *(const float4*)&bias[tc * 4];
  if (MODE == 2 || MODE == 3) {
#pragma unroll
    for (int i = 0; i < 8; i++) {
      int n = n0 + tr * 8 + i;
      if (n < NN) {
        float4 o;
        o.x = acc[i][0] + bv.x; o.y = acc[i][1] + bv.y; o.z = acc[i][2] + bv.z; o.w = acc[i][3] + bv.w;
        if (MODE == 3) { o.x = siluf(o.x); o.y = siluf(o.y); o.z = siluf(o.z); o.w = siluf(o.w); }
        *(float4*)(out + (size_t)n * HH + tc * 4) = o;
      }
    }
  } else {
    float4 gv = *(const float4*)&gg[tc * 4];
    float4 bev = *(const float4*)&bb[tc * 4];
#pragma unroll
    for (int i = 0; i < 8; i++) {
      int n = n0 + tr * 8 + i;
      int nc = (n < NN) ? n : (NN - 1);
      float z0 = acc[i][0] + bv.x, z1 = acc[i][1] + bv.y, z2 = acc[i][2] + bv.z, z3 = acc[i][3] + bv.w;
      if (MODE == 1) {
        float4 hv = *(const float4*)(A0 + (size_t)nc * HH + tc * 4);
        z0 = siluf(z0) + hv.x; z1 = siluf(z1) + hv.y; z2 = siluf(z2) + hv.z; z3 = siluf(z3) + hv.w;
      }
      float mu = warp_sum(z0 + z1 + z2 + z3) * (1.0f / 128.0f);
      float d0 = z0 - mu, d1 = z1 - mu, d2 = z2 - mu, d3 = z3 - mu;
      float var = warp_sum(d0 * d0 + d1 * d1 + d2 * d2 + d3 * d3) * (1.0f / 128.0f);
      float rs = rsqrtf(var + 1e-5f);
      float4 o;
      o.x = d0 * rs * gv.x + bev.x;
      o.y = d1 * rs * gv.y + bev.y;
      o.z = d2 * rs * gv.z + bev.z;
      o.w = d3 * rs * gv.w + bev.w;
      if (MODE == 0) { o.x = siluf(o.x); o.y = siluf(o.y); o.z = siluf(o.z); o.w = siluf(o.w); }
      if (n < NN) *(float4*)(out + (size_t)n * HH + tc * 4) = o;
    }
  }
}

// ------------------------- group id (argmax of x[:,128:154]) + counts -------------------------
__global__ void k_argmax(const float* __restrict__ x) {
  int n = blockIdx.x * blockDim.x + threadIdx.x;
  if (n >= NN) return;
  const float* p = x + (size_t)n * INDIM + 128;
  float best = p[0];
  int bi = 0;
#pragma unroll
  for (int c = 1; c < WYD; c++) {
    float v = p[c];
    if (v > best) { best = v; bi = c; }
  }
  g_gid[n] = bi;
  atomicAdd(&g_gcnt[bi], 1.0f);
}

// ------------------------- o2 GEMM fused with group segment-sum -------------------------
__global__ __launch_bounds__(256) void k_o2(const float* __restrict__ W, const float* __restrict__ b) {
  __shared__ float Ws[32 * CC];
  int tid = threadIdx.x;
  int warp = tid >> 5, lane = tid & 31;
  int n = blockIdx.x * 8 + warp;
  bool valid = n < NN;
  float acc[8];
#pragma unroll
  for (int s = 0; s < 8; s++) acc[s] = 0.f;
#pragma unroll 1
  for (int kc = 0; kc < 4; kc++) {
    __syncthreads();
    for (int i = tid; i < 32 * CC; i += 256) Ws[i] = W[kc * 32 * CC + i];
    __syncthreads();
    float tOwn = valid ? g_h[(size_t)n * HH + kc * 32 + lane] : 0.f;
#pragma unroll
    for (int k = 0; k < 32; k++) {
      float a = __shfl_sync(0xffffffffu, tOwn, k);
#pragma unroll
      for (int s = 0; s < 8; s++) {
        int j = lane + 32 * s;
        if (j < CC) acc[s] = fmaf(a, Ws[k * CC + j], acc[s]);
      }
    }
  }
  if (valid) {
    int gid = g_gid[n];
#pragma unroll
    for (int s = 0; s < 8; s++) {
      int j = lane + 32 * s;
      if (j < CC) atomicAdd(&g_gsum[gid * CC + j], acc[s] + b[j]);
    }
  }
}

__global__ void k_mean() {
  int i = blockIdx.x * blockDim.x + threadIdx.x;
  if (i >= WYD * CC) return;
  g_gmean[i] = g_gsum[i] / fmaxf(g_gcnt[i / CC], 1.0f);
}

__global__ void k_out(float* __restrict__ out) {
  int n = blockIdx.x * 8 + (threadIdx.x >> 5);
  int lane = threadIdx.x & 31;
  if (n >= NN) return;
  const float* src = g_gmean + (size_t)g_gid[n] * CC;
  float* dst = out + (size_t)n * CC;
  for (int c = lane; c < CC; c += 32) dst[c] = src[c];
}

// ------------------------- launch -------------------------
extern "C" void kernel_launch(void* const* d_in, const int* in_sizes, int n_in,
                              void* d_out, int out_size) {
  const float* x = (const float*)d_in[0];
  const int* ei = (const int*)d_in[1];
  const float* ea = (const float*)d_in[2];
  const float* W_in = (const float*)d_in[3];
  const float* b_in = (const float*)d_in[4];
  const float* g_in = (const float*)d_in[5];
  const float* be_in = (const float*)d_in[6];
  const float* W_e = (const float*)d_in[7];
  const float* b_e = (const float*)d_in[8];
  const float* g_e = (const float*)d_in[9];
  const float* be_e = (const float*)d_in[10];
  const float* msg_W1 = (const float*)d_in[11];
  const float* msg_b1 = (const float*)d_in[12];
  const float* msg_W2 = (const float*)d_in[13];
  const float* msg_b2 = (const float*)d_in[14];
  const float* upd_W = (const float*)d_in[15];
  const float* upd_b = (const float*)d_in[16];
  const float* norm_g = (const float*)d_in[17];
  const float* norm_b = (const float*)d_in[18];
  const float* W_jk = (const float*)d_in[19];
  const float* b_jk = (const float*)d_in[20];
  const float* W_o1 = (const float*)d_in[21];
  const float* b_o1 = (const float*)d_in[22];
  const float* W_o2 = (const float*)d_in[23];
  const float* b_o2 = (const float*)d_in[24];
  float* out = (float*)d_out;

  const int NBLK = (NN + 63) / 64;  // 782

  k_zero_misc<<<512, 256>>>();
  k_edge_r_hist<<<(EE + 255) / 256, 256>>>(ea);
  k_select_hi<<<1, 1024>>>();
  k_histlo<<<(EE + 255) / 256, 256>>>();
  k_select_lo<<<1, 1024>>>();
  k_edge_enc<<<EE / 8, 256>>>(ea, W_e, b_e, g_e, be_e);
  k_argmax<<<(NN + 255) / 256, 256>>>(x);
  k_gemm_node<256, 0><<<NBLK, 256>>>(x, W_in, b_in, g_in, be_in, 0);
  for (int l = 0; l < LL; l++) {
    k_zero_m<<<512, 256>>>();
    k_edge_layer<<<EE / 64, 256>>>(ei, msg_W1 + (size_t)l * 384 * HH, msg_b1 + l * HH,
                                   msg_W2 + (size_t)l * HH * HH, msg_b2 + l * HH, l);
    k_gemm_node<256, 1><<<NBLK, 256>>>(x, upd_W + (size_t)l * 256 * HH, upd_b + l * HH,
                                       norm_g + l * HH, norm_b + l * HH, l);
  }
  k_gemm_node<640, 2><<<NBLK, 256>>>(x, W_jk, b_jk, b_jk, b_jk, 0);
  k_gemm_node<128, 3><<<NBLK, 256>>>(x, W_o1, b_o1, b_o1, b_o1, 0);
  k_o2<<<(NN + 7) / 8, 256>>>(W_o2, b_o2);
  k_mean<<<24, 256>>>();
  k_out<<<(NN + 7) / 8, 256>>>(out);
  (void)in_sizes; (void)n_in; (void)out_size;
}

// round 7
// speedup vs baseline: 1.4681x; 1.4681x over previous
#include <cuda_runtime.h>
#include <math.h>

#define NN 50000
#define EE 800000
#define INDIM 256
#define HH 128
#define LL 4
#define CC 230
#define WYD 26
#define SLAB ((size_t)NN * HH)

// ------------------------- device scratch (no allocations allowed) -------------------------
__device__ float g_states[(size_t)(LL + 1) * NN * HH];  // h after each layer (slab l)
__device__ float g_m[(size_t)NN * HH];                  // message accumulator
__device__ float g_t1[(size_t)NN * HH];                 // h_agg
__device__ float g_h[(size_t)NN * HH];                  // silu(o1) temp
__device__ float g_eenc[(size_t)EE * HH];               // edge encodings
__device__ float g_r[EE];
__device__ unsigned g_hist[65536];
__device__ unsigned g_histlo[2 * 65536];
__device__ unsigned g_selhi[2];
__device__ unsigned g_rem[2];
__device__ float g_cand[2];
__device__ float g_rmax;
__device__ int g_gid[NN];
__device__ float g_gsum[WYD * CC];
__device__ float g_gcnt[WYD];
__device__ float g_gmean[WYD * CC];

__device__ __forceinline__ float siluf(float v) { return v / (1.0f + __expf(-v)); }
__device__ __forceinline__ float warp_sum(float v) {
#pragma unroll
  for (int o = 16; o > 0; o >>= 1) v += __shfl_xor_sync(0xffffffffu, v, o);
  return v;
}
__device__ __forceinline__ unsigned tf32u(float x) {
  unsigned u;
  asm("cvt.rna.tf32.f32 %0, %1;" : "=r"(u) : "f"(x));
  return u;
}
__device__ __forceinline__ void mma8(float* c, unsigned a0, unsigned a1, unsigned a2, unsigned a3,
                                     unsigned b0, unsigned b1) {
  asm volatile(
      "mma.sync.aligned.m16n8k8.row.col.f32.tf32.tf32.f32 "
      "{%0,%1,%2,%3},{%4,%5,%6,%7},{%8,%9},{%0,%1,%2,%3};\n"
      : "+f"(c[0]), "+f"(c[1]), "+f"(c[2]), "+f"(c[3])
      : "r"(a0), "r"(a1), "r"(a2), "r"(a3), "r"(b0), "r"(b1));
}

// ------------------------- zero kernel (replay idempotence) -------------------------
__global__ void k_zero_misc() {
  int i = blockIdx.x * blockDim.x + threadIdx.x;
  if (i < 65536) g_hist[i] = 0u;
  if (i < 2 * 65536) g_histlo[i] = 0u;
  if (i < WYD * CC) g_gsum[i] = 0.f;
  if (i < WYD) g_gcnt[i] = 0.f;
}
__global__ void k_zero_m() {
  size_t i = (size_t)blockIdx.x * blockDim.x + threadIdx.x;
  size_t tot = (size_t)NN * HH / 4;
  float4 z = make_float4(0.f, 0.f, 0.f, 0.f);
  for (; i < tot; i += (size_t)gridDim.x * blockDim.x) ((float4*)g_m)[i] = z;
}

// ------------------------- edge r + hi-histogram (fused) -------------------------
__global__ void k_edge_r_hist(const float* __restrict__ ea) {
  int e = blockIdx.x * blockDim.x + threadIdx.x;
  if (e >= EE) return;
  float ax = ea[e * 3 + 0], ay = ea[e * 3 + 1], az = ea[e * 3 + 2];
  float r = fmaxf(sqrtf(ax * ax + ay * ay + az * az), 1e-8f);
  g_r[e] = r;
  unsigned key = __float_as_uint(r);  // positive floats: bit order == value order
  atomicAdd(&g_hist[key >> 16], 1u);
}
__global__ void k_select_hi() {
  __shared__ unsigned s[1024];
  int tid = threadIdx.x;
  unsigned local = 0;
  for (int i = 0; i < 64; i++) local += g_hist[tid * 64 + i];
  s[tid] = local;
  __syncthreads();
  for (int off = 1; off < 1024; off <<= 1) {
    unsigned v = (tid >= off) ? s[tid - off] : 0u;
    __syncthreads();
    s[tid] += v;
    __syncthreads();
  }
  unsigned incl = s[tid], excl = incl - local;
  unsigned ranks[2] = {759999u, 760000u};  // floor/ceil of 0.95*(E-1)
  for (int j = 0; j < 2; j++) {
    unsigned R = ranks[j];
    if (R >= excl && R < incl) {
      unsigned cum = excl;
      for (int i = 0; i < 64; i++) {
        unsigned c = g_hist[tid * 64 + i];
        if (R < cum + c) { g_selhi[j] = (unsigned)(tid * 64 + i); g_rem[j] = R - cum; break; }
        cum += c;
      }
    }
  }
}
__global__ void k_histlo() {
  int e = blockIdx.x * blockDim.x + threadIdx.x;
  if (e >= EE) return;
  unsigned key = __float_as_uint(g_r[e]);
  unsigned hi = key >> 16, lo = key & 0xffffu;
  if (hi == g_selhi[0]) atomicAdd(&g_histlo[lo], 1u);
  if (hi == g_selhi[1]) atomicAdd(&g_histlo[65536 + lo], 1u);
}
__global__ void k_select_lo() {
  __shared__ unsigned s[1024];
  int tid = threadIdx.x;
  for (int j = 0; j < 2; j++) {
    const unsigned* h = g_histlo + j * 65536;
    unsigned local = 0;
    for (int i = 0; i < 64; i++) local += h[tid * 64 + i];
    s[tid] = local;
    __syncthreads();
    for (int off = 1; off < 1024; off <<= 1) {
      unsigned v = (tid >= off) ? s[tid - off] : 0u;
      __syncthreads();
      s[tid] += v;
      __syncthreads();
    }
    unsigned incl = s[tid], excl = incl - local;
    unsigned R = g_rem[j];
    if (R >= excl && R < incl) {
      unsigned cum = excl;
      for (int i = 0; i < 64; i++) {
        unsigned c = h[tid * 64 + i];
        if (R < cum + c) {
          g_cand[j] = __uint_as_float((g_selhi[j] << 16) | (unsigned)(tid * 64 + i));
          break;
        }
        cum += c;
      }
    }
    __syncthreads();
  }
  if (tid == 0) {
    // match JAX fp32 quantile arithmetic: index = q*(n-1) in f32
    float pos = 0.95f * (float)(EE - 1);
    float fl = floorf(pos);
    float frac = pos - fl;
    float v = g_cand[0] * (1.0f - frac) + g_cand[1] * frac;
    g_rmax = fminf(fmaxf(v, 1.0f), 8.0f);
  }
}

// ------------------------- edge encoder: e_enc = LN(silu([u,r,rbf] @ W_e + b_e)) -------------------------
__global__ __launch_bounds__(256) void k_edge_enc(const float* __restrict__ ea,
                                                  const float* __restrict__ We,
                                                  const float* __restrict__ be,
                                                  const float* __restrict__ ge,
                                                  const float* __restrict__ bee) {
  int e = blockIdx.x * 8 + (threadIdx.x >> 5);
  int lane = threadIdx.x & 31;
  if (e >= EE) return;  // uniform per warp
  float r = g_r[e];
  float inv = 1.0f / r;
  float comp = (lane < 3) ? ea[e * 3 + lane] : 0.f;
  float rmax = g_rmax;
  float d = fmaxf(rmax * (1.0f / 15.0f), 0.001f);
  float gamma = 1.0f / (0.5f * d * d);  // == 1/(2*(0.5*delta)^2)
  float fv = 0.f;
  if (lane < 3) fv = comp * inv;
  else if (lane == 3) fv = r;
  else if (lane < 20) {
    int k = lane - 4;
    float c = rmax * ((float)k / 15.0f);
    float t = r - c;
    fv = __expf(-gamma * t * t);
  }
  float4 acc = *(const float4*)&be[lane * 4];
#pragma unroll
  for (int k = 0; k < 20; k++) {
    float a = __shfl_sync(0xffffffffu, fv, k);
    float4 wv = *(const float4*)&We[k * HH + lane * 4];
    acc.x = fmaf(a, wv.x, acc.x);
    acc.y = fmaf(a, wv.y, acc.y);
    acc.z = fmaf(a, wv.z, acc.z);
    acc.w = fmaf(a, wv.w, acc.w);
  }
  acc.x = siluf(acc.x); acc.y = siluf(acc.y); acc.z = siluf(acc.z); acc.w = siluf(acc.w);
  float mu = warp_sum(acc.x + acc.y + acc.z + acc.w) * (1.0f / 128.0f);
  float d0 = acc.x - mu, d1 = acc.y - mu, d2 = acc.z - mu, d3 = acc.w - mu;
  float var = warp_sum(d0 * d0 + d1 * d1 + d2 * d2 + d3 * d3) * (1.0f / 128.0f);
  float rs = rsqrtf(var + 1e-5f);
  float4 gv = *(const float4*)&ge[lane * 4];
  float4 bv = *(const float4*)&bee[lane * 4];
  float4 o;
  o.x = d0 * rs * gv.x + bv.x;
  o.y = d1 * rs * gv.y + bv.y;
  o.z = d2 * rs * gv.z + bv.z;
  o.w = d3 * rs * gv.w + bv.w;
  *(float4*)&g_eenc[(size_t)e * HH + lane * 4] = o;
}

// ------------------------- fused edge message layer (tf32 tensor cores) -------------------------
// 64 edges/block, 256 threads (8 warps). Warp (wr=w>>1, wc=w&1) computes rows [wr*16,+16),
// cols [wc*64,+64) via mma.sync m16n8k8 tf32.
// GEMM1: gathered (64x384) @ W1 (384x128) -> silu -> Cs (tf32) -> GEMM2: @ W2 (128x128)
// -> silu -> atomicAdd into g_m[dst].
// Dynamic smem layout (uints): Bs[32][136] | Cs[64][136] (As[64][40] aliases Cs) | idx[128]
#define SMEM_TC ((32 * 136 + 64 * 136 + 128) * 4)
__global__ __launch_bounds__(256) void k_edge_layer_tc(const int* __restrict__ ei,
                                                       const float* __restrict__ W1,
                                                       const float* __restrict__ b1f,
                                                       const float* __restrict__ W2,
                                                       const float* __restrict__ b2f, int l) {
  extern __shared__ __align__(16) unsigned sm[];
  unsigned* Bs = sm;                  // [32][136]
  unsigned* Cs = sm + 32 * 136;       // [64][136]
  unsigned* As = Cs;                  // alias: [64][40] = 2560 uints < 64*136
  int* sIdx = (int*)(sm + 32 * 136 + 64 * 136);  // [128]: src 0..63, dst 64..127
  const float* h = g_states + (size_t)l * SLAB;
  int tid = threadIdx.x, lane = tid & 31, w = tid >> 5;
  int gid = lane >> 2, tig = lane & 3;
  int wr = w >> 1, wc = w & 1;
  int e0 = blockIdx.x * 64;
  if (tid < 128) sIdx[tid] = (tid < 64) ? ei[e0 + tid] : ei[EE + e0 + tid - 64];

  float acc[8][4];
#pragma unroll
  for (int nb = 0; nb < 8; nb++)
#pragma unroll
    for (int j = 0; j < 4; j++) acc[nb][j] = 0.f;

  // ---------------- GEMM1: K = 384 in 12 chunks of 32 ----------------
#pragma unroll 1
  for (int c = 0; c < 12; c++) {
    int col0 = c * 32;
    __syncthreads();
    {  // stage A: 64 rows x 32 cols gathered, cvt to tf32
      int row = tid >> 2, q = tid & 3;
      const float* p;
      if (col0 < 128) p = h + (size_t)sIdx[row] * HH + col0;
      else if (col0 < 256) p = h + (size_t)sIdx[64 + row] * HH + (col0 - 128);
      else p = g_eenc + (size_t)(e0 + row) * HH + (col0 - 256);
      float4 v0 = *(const float4*)(p + q * 4);
      float4 v1 = *(const float4*)(p + q * 4 + 16);
      uint4 u0, u1;
      u0.x = tf32u(v0.x); u0.y = tf32u(v0.y); u0.z = tf32u(v0.z); u0.w = tf32u(v0.w);
      u1.x = tf32u(v1.x); u1.y = tf32u(v1.y); u1.z = tf32u(v1.z); u1.w = tf32u(v1.w);
      *(uint4*)&As[row * 40 + q * 4] = u0;
      *(uint4*)&As[row * 40 + q * 4 + 16] = u1;
    }
    {  // stage B: 32 rows x 128 cols of W1, cvt to tf32
      int row = tid >> 3, cg = tid & 7;
      const float* p = W1 + (size_t)(col0 + row) * HH + cg * 16;
#pragma unroll
      for (int j = 0; j < 4; j++) {
        float4 v = *(const float4*)(p + j * 4);
        uint4 u;
        u.x = tf32u(v.x); u.y = tf32u(v.y); u.z = tf32u(v.z); u.w = tf32u(v.w);
        *(uint4*)&Bs[row * 136 + cg * 16 + j * 4] = u;
      }
    }
    __syncthreads();
    int ar = wr * 16 + gid;
#pragma unroll
    for (int ks = 0; ks < 4; ks++) {
      int kb = ks * 8;
      unsigned a0 = As[ar * 40 + kb + tig];
      unsigned a1 = As[(ar + 8) * 40 + kb + tig];
      unsigned a2 = As[ar * 40 + kb + tig + 4];
      unsigned a3 = As[(ar + 8) * 40 + kb + tig + 4];
#pragma unroll
      for (int nb = 0; nb < 8; nb++) {
        int col = wc * 64 + nb * 8 + gid;
        unsigned b0 = Bs[(kb + tig) * 136 + col];
        unsigned b1r = Bs[(kb + tig + 4) * 136 + col];
        mma8(acc[nb], a0, a1, a2, a3, b0, b1r);
      }
    }
  }
  __syncthreads();  // all As reads done before Cs (alias) is written

  // ---------------- epilogue1: silu(acc + b1) -> Cs as tf32 ----------------
  {
    int r0 = wr * 16 + gid;
#pragma unroll
    for (int nb = 0; nb < 8; nb++) {
      int cb = wc * 64 + nb * 8 + 2 * tig;
      float bi0 = b1f[cb], bi1 = b1f[cb + 1];
      Cs[r0 * 136 + cb] = tf32u(siluf(acc[nb][0] + bi0));
      Cs[r0 * 136 + cb + 1] = tf32u(siluf(acc[nb][1] + bi1));
      Cs[(r0 + 8) * 136 + cb] = tf32u(siluf(acc[nb][2] + bi0));
      Cs[(r0 + 8) * 136 + cb + 1] = tf32u(siluf(acc[nb][3] + bi1));
      acc[nb][0] = 0.f; acc[nb][1] = 0.f; acc[nb][2] = 0.f; acc[nb][3] = 0.f;
    }
  }

  // ---------------- GEMM2: K = 128 in 4 chunks of 32, A = Cs in-place ----------------
#pragma unroll 1
  for (int c = 0; c < 4; c++) {
    int col0 = c * 32;
    __syncthreads();  // Cs visible (1st iter); previous Bs consumed (later iters)
    {
      int row = tid >> 3, cg = tid & 7;
      const float* p = W2 + (size_t)(col0 + row) * HH + cg * 16;
#pragma unroll
      for (int j = 0; j < 4; j++) {
        float4 v = *(const float4*)(p + j * 4);
        uint4 u;
        u.x = tf32u(v.x); u.y = tf32u(v.y); u.z = tf32u(v.z); u.w = tf32u(v.w);
        *(uint4*)&Bs[row * 136 + cg * 16 + j * 4] = u;
      }
    }
    __syncthreads();
    int ar = wr * 16 + gid;
#pragma unroll
    for (int ks = 0; ks < 4; ks++) {
      int kg = col0 + ks * 8;
      unsigned a0 = Cs[ar * 136 + kg + tig];
      unsigned a1 = Cs[(ar + 8) * 136 + kg + tig];
      unsigned a2 = Cs[ar * 136 + kg + tig + 4];
      unsigned a3 = Cs[(ar + 8) * 136 + kg + tig + 4];
#pragma unroll
      for (int nb = 0; nb < 8; nb++) {
        int col = wc * 64 + nb * 8 + gid;
        unsigned b0 = Bs[(ks * 8 + tig) * 136 + col];
        unsigned b1r = Bs[(ks * 8 + tig + 4) * 136 + col];
        mma8(acc[nb], a0, a1, a2, a3, b0, b1r);
      }
    }
  }

  // ---------------- final epilogue: silu(acc + b2) scattered to g_m[dst] ----------------
  {
    int r0 = wr * 16 + gid;
    int d0 = sIdx[64 + r0];
    int d1 = sIdx[64 + r0 + 8];
    float* m0 = g_m + (size_t)d0 * HH;
    float* m1 = g_m + (size_t)d1 * HH;
#pragma unroll
    for (int nb = 0; nb < 8; nb++) {
      int cb = wc * 64 + nb * 8 + 2 * tig;
      float bi0 = b2f[cb], bi1 = b2f[cb + 1];
      atomicAdd(m0 + cb, siluf(acc[nb][0] + bi0));
      atomicAdd(m0 + cb + 1, siluf(acc[nb][1] + bi1));
      atomicAdd(m1 + cb, siluf(acc[nb][2] + bi0));
      atomicAdd(m1 + cb + 1, siluf(acc[nb][3] + bi1));
    }
  }
}

// ------------------------- node-side block GEMMs -------------------------
// MODE 0: out = silu(LN(x @ W + b))              (A = x, K=256)      -> states[0]
// MODE 1: out = LN(silu([h,m] @ W + b) + h)      (K=256)             -> states[l+1]
// MODE 2: out = concat(states) @ W + b           (K=640)             -> g_t1
// MODE 3: out = silu(g_t1 @ W + b)               (K=128)             -> g_h
template <int KD, int MODE>
__global__ __launch_bounds__(256) void k_gemm_node(const float* __restrict__ Ain,
                                                   const float* __restrict__ W,
                                                   const float* __restrict__ bias,
                                                   const float* __restrict__ gg,
                                                   const float* __restrict__ bb, int l) {
  __shared__ __align__(16) float Bs[16][128];
  __shared__ __align__(16) float As[64][16];
  int tid = threadIdx.x;
  int tr = tid >> 5, tc = tid & 31;
  int n0 = blockIdx.x * 64;
  const float* A0;
  const float* A1 = nullptr;
  float* out;
  if (MODE == 0) { A0 = Ain; out = g_states; }
  else if (MODE == 1) { A0 = g_states + (size_t)l * SLAB; A1 = g_m; out = g_states + (size_t)(l + 1) * SLAB; }
  else if (MODE == 2) { A0 = g_states; out = g_t1; }
  else { A0 = g_t1; out = g_h; }
  float acc[8][4];
#pragma unroll
  for (int i = 0; i < 8; i++) { acc[i][0] = 0.f; acc[i][1] = 0.f; acc[i][2] = 0.f; acc[i][3] = 0.f; }
#pragma unroll 1
  for (int c = 0; c < KD / 16; c++) {
    int col0 = c * 16;
    __syncthreads();
    {
      int row = tid >> 2, q = tid & 3;
      int n = n0 + row;
      if (n >= NN) n = NN - 1;
      const float* p;
      if (MODE == 0) p = A0 + (size_t)n * INDIM + col0;
      else if (MODE == 1) p = (col0 < 128) ? (A0 + (size_t)n * HH + col0) : (A1 + (size_t)n * HH + (col0 - 128));
      else if (MODE == 2) p = A0 + (size_t)(col0 >> 7) * SLAB + (size_t)n * HH + (col0 & 127);
      else p = A0 + (size_t)n * HH + col0;
      *(float4*)&As[row][q * 4] = *(const float4*)(p + q * 4);
    }
#pragma unroll
    for (int it = 0; it < 2; it++) {
      int idx = tid * 2 + it;
      int rr = idx >> 5, cc = idx & 31;
      *(float4*)&Bs[rr][cc * 4] = *(const float4*)(W + (size_t)(col0 + rr) * HH + cc * 4);
    }
    __syncthreads();
#pragma unroll
    for (int k = 0; k < 16; k++) {
      float4 b = *(float4*)&Bs[k][tc * 4];
#pragma unroll
      for (int i = 0; i < 8; i++) {
        float a = As[tr * 8 + i][k];
        acc[i][0] = fmaf(a, b.x, acc[i][0]);
        acc[i][1] = fmaf(a, b.y, acc[i][1]);
        acc[i][2] = fmaf(a, b.z, acc[i][2]);
        acc[i][3] = fmaf(a, b.w, acc[i][3]);
      }
    }
  }
  float4 bv = *(const float4*)&bias[tc * 4];
  if (MODE == 2 || MODE == 3) {
#pragma unroll
    for (int i = 0; i < 8; i++) {
      int n = n0 + tr * 8 + i;
      if (n < NN) {
        float4 o;
        o.x = acc[i][0] + bv.x; o.y = acc[i][1] + bv.y; o.z = acc[i][2] + bv.z; o.w = acc[i][3] + bv.w;
        if (MODE == 3) { o.x = siluf(o.x); o.y = siluf(o.y); o.z = siluf(o.z); o.w = siluf(o.w); }
        *(float4*)(out + (size_t)n * HH + tc * 4) = o;
      }
    }
  } else {
    float4 gv = *(const float4*)&gg[tc * 4];
    float4 bev = *(const float4*)&bb[tc * 4];
#pragma unroll
    for (int i = 0; i < 8; i++) {
      int n = n0 + tr * 8 + i;
      int nc = (n < NN) ? n : (NN - 1);
      float z0 = acc[i][0] + bv.x, z1 = acc[i][1] + bv.y, z2 = acc[i][2] + bv.z, z3 = acc[i][3] + bv.w;
      if (MODE == 1) {
        float4 hv = *(const float4*)(A0 + (size_t)nc * HH + tc * 4);
        z0 = siluf(z0) + hv.x; z1 = siluf(z1) + hv.y; z2 = siluf(z2) + hv.z; z3 = siluf(z3) + hv.w;
      }
      float mu = warp_sum(z0 + z1 + z2 + z3) * (1.0f / 128.0f);
      float d0 = z0 - mu, d1 = z1 - mu, d2 = z2 - mu, d3 = z3 - mu;
      float var = warp_sum(d0 * d0 + d1 * d1 + d2 * d2 + d3 * d3) * (1.0f / 128.0f);
      float rs = rsqrtf(var + 1e-5f);
      float4 o;
      o.x = d0 * rs * gv.x + bev.x;
      o.y = d1 * rs * gv.y + bev.y;
      o.z = d2 * rs * gv.z + bev.z;
      o.w = d3 * rs * gv.w + bev.w;
      if (MODE == 0) { o.x = siluf(o.x); o.y = siluf(o.y); o.z = siluf(o.z); o.w = siluf(o.w); }
      if (n < NN) *(float4*)(out + (size_t)n * HH + tc * 4) = o;
    }
  }
}

// ------------------------- group id (argmax of x[:,128:154]) + counts -------------------------
__global__ void k_argmax(const float* __restrict__ x) {
  int n = blockIdx.x * blockDim.x + threadIdx.x;
  if (n >= NN) return;
  const float* p = x + (size_t)n * INDIM + 128;
  float best = p[0];
  int bi = 0;
#pragma unroll
  for (int c = 1; c < WYD; c++) {
    float v = p[c];
    if (v > best) { best = v; bi = c; }
  }
  g_gid[n] = bi;
  atomicAdd(&g_gcnt[bi], 1.0f);
}

// ------------------------- o2 GEMM fused with group segment-sum -------------------------
__global__ __launch_bounds__(256) void k_o2(const float* __restrict__ W, const float* __restrict__ b) {
  __shared__ float Ws[32 * CC];
  int tid = threadIdx.x;
  int warp = tid >> 5, lane = tid & 31;
  int n = blockIdx.x * 8 + warp;
  bool valid = n < NN;
  float acc[8];
#pragma unroll
  for (int s = 0; s < 8; s++) acc[s] = 0.f;
#pragma unroll 1
  for (int kc = 0; kc < 4; kc++) {
    __syncthreads();
    for (int i = tid; i < 32 * CC; i += 256) Ws[i] = W[kc * 32 * CC + i];
    __syncthreads();
    float tOwn = valid ? g_h[(size_t)n * HH + kc * 32 + lane] : 0.f;
#pragma unroll
    for (int k = 0; k < 32; k++) {
      float a = __shfl_sync(0xffffffffu, tOwn, k);
#pragma unroll
      for (int s = 0; s < 8; s++) {
        int j = lane + 32 * s;
        if (j < CC) acc[s] = fmaf(a, Ws[k * CC + j], acc[s]);
      }
    }
  }
  if (valid) {
    int gid = g_gid[n];
#pragma unroll
    for (int s = 0; s < 8; s++) {
      int j = lane + 32 * s;
      if (j < CC) atomicAdd(&g_gsum[gid * CC + j], acc[s] + b[j]);
    }
  }
}

__global__ void k_mean() {
  int i = blockIdx.x * blockDim.x + threadIdx.x;
  if (i >= WYD * CC) return;
  g_gmean[i] = g_gsum[i] / fmaxf(g_gcnt[i / CC], 1.0f);
}

__global__ void k_out(float* __restrict__ out) {
  int n = blockIdx.x * 8 + (threadIdx.x >> 5);
  int lane = threadIdx.x & 31;
  if (n >= NN) return;
  const float* src = g_gmean + (size_t)g_gid[n] * CC;
  float* dst = out + (size_t)n * CC;
  for (int c = lane; c < CC; c += 32) dst[c] = src[c];
}

// ------------------------- launch -------------------------
extern "C" void kernel_launch(void* const* d_in, const int* in_sizes, int n_in,
                              void* d_out, int out_size) {
  const float* x = (const float*)d_in[0];
  const int* ei = (const int*)d_in[1];
  const float* ea = (const float*)d_in[2];
  const float* W_in = (const float*)d_in[3];
  const float* b_in = (const float*)d_in[4];
  const float* g_in = (const float*)d_in[5];
  const float* be_in = (const float*)d_in[6];
  const float* W_e = (const float*)d_in[7];
  const float* b_e = (const float*)d_in[8];
  const float* g_e = (const float*)d_in[9];
  const float* be_e = (const float*)d_in[10];
  const float* msg_W1 = (const float*)d_in[11];
  const float* msg_b1 = (const float*)d_in[12];
  const float* msg_W2 = (const float*)d_in[13];
  const float* msg_b2 = (const float*)d_in[14];
  const float* upd_W = (const float*)d_in[15];
  const float* upd_b = (const float*)d_in[16];
  const float* norm_g = (const float*)d_in[17];
  const float* norm_b = (const float*)d_in[18];
  const float* W_jk = (const float*)d_in[19];
  const float* b_jk = (const float*)d_in[20];
  const float* W_o1 = (const float*)d_in[21];
  const float* b_o1 = (const float*)d_in[22];
  const float* W_o2 = (const float*)d_in[23];
  const float* b_o2 = (const float*)d_in[24];
  float* out = (float*)d_out;

  const int NBLK = (NN + 63) / 64;  // 782

  cudaFuncSetAttribute(k_edge_layer_tc, cudaFuncAttributeMaxDynamicSharedMemorySize, SMEM_TC);

  k_zero_misc<<<512, 256>>>();
  k_edge_r_hist<<<(EE + 255) / 256, 256>>>(ea);
  k_select_hi<<<1, 1024>>>();
  k_histlo<<<(EE + 255) / 256, 256>>>();
  k_select_lo<<<1, 1024>>>();
  k_edge_enc<<<EE / 8, 256>>>(ea, W_e, b_e, g_e, be_e);
  k_argmax<<<(NN + 255) / 256, 256>>>(x);
  k_gemm_node<256, 0><<<NBLK, 256>>>(x, W_in, b_in, g_in, be_in, 0);
  for (int l = 0; l < LL; l++) {
    k_zero_m<<<512, 256>>>();
    k_edge_layer_tc<<<EE / 64, 256, SMEM_TC>>>(ei, msg_W1 + (size_t)l * 384 * HH, msg_b1 + l * HH,
                                               msg_W2 + (size_t)l * HH * HH, msg_b2 + l * HH, l);
    k_gemm_node<256, 1><<<NBLK, 256>>>(x, upd_W + (size_t)l * 256 * HH, upd_b + l * HH,
                                       norm_g + l * HH, norm_b + l * HH, l);
  }
  k_gemm_node<640, 2><<<NBLK, 256>>>(x, W_jk, b_jk, b_jk, b_jk, 0);
  k_gemm_node<128, 3><<<NBLK, 256>>>(x, W_o1, b_o1, b_o1, b_o1, 0);
  k_o2<<<(NN + 7) / 8, 256>>>(W_o2, b_o2);
  k_mean<<<24, 256>>>();
  k_out<<<(NN + 7) / 8, 256>>>(out);
  (void)in_sizes; (void)n_in; (void)out_size;
}